// round 16
// baseline (speedup 1.0000x reference)
#include <cuda_runtime.h>

typedef unsigned long long ull;

#define NT     8
#define NRES   500
#define NBINS  34
#define NHALF  17
#define KCB    150.0f
#define WP2    19      // float2 entries per row (17 used + pad): 38-word stride, conflict-free
#define ROWS   64
#define NCHUNK 8

__device__ __forceinline__ float ex2a(float x)  { float r; asm("ex2.approx.ftz.f32 %0, %1;"  : "=f"(r) : "f"(x)); return r; }
__device__ __forceinline__ float frcpa(float x) { float r; asm("rcp.approx.ftz.f32 %0, %1;"  : "=f"(r) : "f"(x)); return r; }
__device__ __forceinline__ float fsqrta(float x){ float r; asm("sqrt.approx.ftz.f32 %0, %1;" : "=f"(r) : "f"(x)); return r; }

__device__ __forceinline__ ull pk2(float lo, float hi) {
    ull r; asm("mov.b64 %0, {%1, %2};" : "=l"(r) : "f"(lo), "f"(hi)); return r;
}
__device__ __forceinline__ float2 upk2(ull v) {
    float2 f; asm("mov.b64 {%0, %1}, %2;" : "=f"(f.x), "=f"(f.y) : "l"(v)); return f;
}
__device__ __forceinline__ ull mul2_(ull a, ull b) {
    ull r; asm("mul.rn.f32x2 %0, %1, %2;" : "=l"(r) : "l"(a), "l"(b)); return r;
}
__device__ __forceinline__ ull add2_(ull a, ull b) {
    ull r; asm("add.rn.f32x2 %0, %1, %2;" : "=l"(r) : "l"(a), "l"(b)); return r;
}
__device__ __forceinline__ ull fma2_(ull a, ull b, ull c) {
    ull r; asm("fma.rn.f32x2 %0, %1, %2, %3;" : "=l"(r) : "l"(a), "l"(b), "l"(c)); return r;
}

// Uniform-grid fast path, constant-multiplier recurrence:
//   g_b = g0 * E^b * T_b,  E = exp(z0*delta),  T_b = exp(-b^2 delta^2/2) (data-indep)
//   T folded into staged weights. Packed f32x2 lanes = (fwd chain, bwd chain)
//   of one trajectory; staged pair (w_k*T_k, w_{33-k}*T_k) -> 1 LDS.64/k for
//   both trajectories. Moments + U-trick:
//   F = (z0-17d)*S0f + (z0-16d)*S0b + d*(Uf - Ub);  coef = (K/sigma^2)*F/dist.
__global__ __launch_bounds__(256, 5) void force_folder_kernel(
    const float* __restrict__ coords,   // [NT, NRES, 3]
    const float* __restrict__ gw,       // [NRES, NRES, NBINS]
    const float* __restrict__ centres,  // [NBINS]
    const float* __restrict__ sigmas,   // [NBINS]
    float* __restrict__ out)            // [NT, NRES, 3], pre-zeroed
{
    const int chunk = blockIdx.x;
    const int j     = blockIdx.y;
    const int tid   = threadIdx.x;
    const int warp  = tid >> 5;
    const int lane  = tid & 31;
    const int tg    = tid >> 6;     // 0..3 -> trajs {2tg, 2tg+1}
    const int il    = tid & 63;     // i-row lane

    __shared__ float2 s_wt[ROWS * WP2];  // (wT_fwd_k, wT_bwd_k) per row
    __shared__ float  s_T[NHALF];
    __shared__ float  s_cbj[NT * 3];
    __shared__ float  s_part[8][6];

    const float c0 = __ldg(centres);
    const float dc = __ldg(centres + 1) - c0;
    const float sg = __ldg(sigmas);
    const float invs  = 1.0f / sg;
    const float delta = dc * invs;
    const float Cq    = -0.72134752044f;              // -0.5 * log2(e)
    const float A     = delta * 1.44269504089f;       // delta * log2(e)

    if (tid < NT * 3) {
        int t = tid / 3, cc = tid - t * 3;
        s_cbj[tid] = coords[(t * NRES + j) * 3 + cc];
    }
    if (tid < NHALF) {
        float kd = (float)tid * delta;
        s_T[tid] = ex2a(Cq * kd * kd);               // T_k = exp(-k^2 d^2 / 2)
    }
    int okp = 1;
    if (tid < NBINS) {
        float cb = __ldg(centres + tid);
        float sb = __ldg(sigmas + tid);
        okp = (fabsf(sb - sg) <= 1e-5f * fabsf(sg)) &&
              (fabsf(cb - fmaf((float)tid, dc, c0)) <= 1e-4f * (fabsf(cb) + 1.0f));
    }
    const int uniform = __syncthreads_and(okp);      // also orders s_T for staging

    // ---- Staging: warp w stages rows [w*8, w*8+8). Entry k of a row holds
    // (w_k * T_k, w_{33-k} * T_k)  (T=1 on the non-uniform fallback). ----
    {
        float* swf = (float*)s_wt;
        const int rbase = warp * 8;
        #pragma unroll
        for (int it = 0; it < 5; it++) {
            int k = it * 32 + lane;
            if (k < 8 * 17) {
                int r = k / 17;
                int c = k - r * 17;
                int rl = rbase + r;
                int rg2 = min(chunk * ROWS + rl, NRES - 1);
                const float2 w2 = *(const float2*)(gw + ((long)rg2 * NRES + j) * NBINS + 2 * c);
                int b0 = 2 * c, b1 = 2 * c + 1;
                int e0 = min(b0, 33 - b0), h0 = (b0 > 16);
                int e1 = min(b1, 33 - b1), h1 = (b1 > 16);
                float t0 = uniform ? s_T[e0] : 1.0f;
                float t1 = uniform ? s_T[e1] : 1.0f;
                swf[(rl * WP2 + e0) * 2 + h0] = w2.x * t0;
                swf[(rl * WP2 + e1) * 2 + h1] = w2.y * t1;
            }
        }
    }
    __syncthreads();

    float acc[2][3];
    #pragma unroll
    for (int tl = 0; tl < 2; tl++) { acc[tl][0] = 0.f; acc[tl][1] = 0.f; acc[tl][2] = 0.f; }

    const int i = chunk * ROWS + il;
    if (i < NRES) {
        const float2* __restrict__ wrow2 = s_wt + il * WP2;

        float d[2], F[2], dxs[2], dys[2], dzs[2];
        #pragma unroll
        for (int tl = 0; tl < 2; tl++) {
            int t = tg * 2 + tl;
            const float* ci = coords + (t * NRES + i) * 3;
            float dx = s_cbj[t * 3 + 0] - ci[0];
            float dy = s_cbj[t * 3 + 1] - ci[1];
            float dz = s_cbj[t * 3 + 2] - ci[2];
            dxs[tl] = dx; dys[tl] = dy; dzs[tl] = dz;
            float ss = fmaf(dx, dx, fmaf(dy, dy, dz * dz));
            d[tl] = fminf(fmaxf(fsqrta(ss), 0.1f), 40.0f);
        }

        float cs;   // final: coef = cs * F * (1/dist)
        if (uniform) {
            const float mc0 = -c0 * invs;
            float z0s[2];
            ull P2[2], E2[2], S0[2], U2[2];
            #pragma unroll
            for (int tl = 0; tl < 2; tl++) {
                float z0  = fmaf(d[tl], invs, mc0);
                float z33 = z0 - 33.0f * delta;
                z0s[tl] = z0;
                // anchors: P = (g0, g33), constant multipliers E = (e^{z0 d}, e^{-z33 d})
                P2[tl] = pk2(ex2a(Cq * z0 * z0), ex2a(Cq * z33 * z33));
                E2[tl] = pk2(ex2a(z0 * A),       ex2a(-z33 * A));
                S0[tl] = 0ull;
                U2[tl] = 0ull;
            }

            #pragma unroll
            for (int k = 0; k < NHALF; k++) {
                ull wt = *(const ull*)&wrow2[k];     // (wT_fwd_k, wT_bwd_k)
                #pragma unroll
                for (int tl = 0; tl < 2; tl++) {
                    S0[tl] = fma2_(wt, P2[tl], S0[tl]);
                    U2[tl] = add2_(U2[tl], S0[tl]);
                    P2[tl] = mul2_(P2[tl], E2[tl]);
                }
            }

            #pragma unroll
            for (int tl = 0; tl < 2; tl++) {
                float2 s0 = upk2(S0[tl]);            // (S0f, S0b)
                float2 uu = upk2(U2[tl]);            // (Uf, Ub)
                float e0 = z0s[tl] - 17.0f * delta;
                float e1 = z0s[tl] - 16.0f * delta;
                F[tl] = fmaf(e0, s0.x, fmaf(e1, s0.y, delta * (uu.x - uu.y)));
            }
            cs = KCB * invs * invs;
        } else {
            // generic fallback (non-uniform bins): reference-accurate scalar path
            F[0] = 0.0f; F[1] = 0.0f;
            for (int b = 0; b < NBINS; b++) {
                float cb  = __ldg(centres + b);
                float sb  = __ldg(sigmas + b);
                float isb = 1.0f / sb;
                float2 wp = wrow2[min(b, 33 - b)];
                float w   = ((b <= 16) ? wp.x : wp.y) * isb * isb * isb;
                #pragma unroll
                for (int tl = 0; tl < 2; tl++) {
                    float u = (d[tl] - cb) * isb;
                    float e = ex2a(Cq * u * u);
                    F[tl] = fmaf(-u * w, e, F[tl]);
                }
            }
            cs = -KCB;
        }

        #pragma unroll
        for (int tl = 0; tl < 2; tl++) {
            float coef = cs * F[tl] * frcpa(d[tl]);
            acc[tl][0] = fmaf(coef, dxs[tl], acc[tl][0]);
            acc[tl][1] = fmaf(coef, dys[tl], acc[tl][1]);
            acc[tl][2] = fmaf(coef, dzs[tl], acc[tl][2]);
        }
    }

    // ---- Reduce 32 i-lanes per warp; 2 warps per tg; atomic to out ----
    #pragma unroll
    for (int tl = 0; tl < 2; tl++) {
        #pragma unroll
        for (int c = 0; c < 3; c++) {
            float val = acc[tl][c];
            val += __shfl_down_sync(0xffffffffu, val, 16);
            val += __shfl_down_sync(0xffffffffu, val, 8);
            val += __shfl_down_sync(0xffffffffu, val, 4);
            val += __shfl_down_sync(0xffffffffu, val, 2);
            val += __shfl_down_sync(0xffffffffu, val, 1);
            if (lane == 0) s_part[warp][tl * 3 + c] = val;
        }
    }
    __syncthreads();
    if (tid < 24) {
        int tg2 = tid / 6, idx = tid - tg2 * 6;
        float s = s_part[tg2 * 2 + 0][idx] + s_part[tg2 * 2 + 1][idx];
        int tl = idx / 3, c = idx - tl * 3;
        int t = tg2 * 2 + tl;
        atomicAdd(&out[(t * NRES + j) * 3 + c], s);
    }
}

extern "C" void kernel_launch(void* const* d_in, const int* in_sizes, int n_in,
                              void* d_out, int out_size) {
    const float* coords  = (const float*)d_in[0];
    const float* gw      = (const float*)d_in[1];
    const float* centres = (const float*)d_in[2];
    const float* sigmas  = (const float*)d_in[3];
    float* out = (float*)d_out;

    cudaMemsetAsync(out, 0, (size_t)out_size * sizeof(float));  // graph memset node
    dim3 grid(NCHUNK, NRES);
    force_folder_kernel<<<grid, 256>>>(coords, gw, centres, sigmas, out);
}

// round 17
// speedup vs baseline: 1.0094x; 1.0094x over previous
#include <cuda_runtime.h>

typedef unsigned long long ull;

#define NT     8
#define NRES   500
#define NBINS  34
#define NHALF  17
#define KCB    150.0f
#define WP2    19      // float2 entries per row: 38-word stride, conflict-free LDS.64
#define ROWS   64
#define NCHUNK 8

__device__ __forceinline__ float ex2a(float x)  { float r; asm("ex2.approx.ftz.f32 %0, %1;"  : "=f"(r) : "f"(x)); return r; }
__device__ __forceinline__ float frcpa(float x) { float r; asm("rcp.approx.ftz.f32 %0, %1;"  : "=f"(r) : "f"(x)); return r; }
__device__ __forceinline__ float fsqrta(float x){ float r; asm("sqrt.approx.ftz.f32 %0, %1;" : "=f"(r) : "f"(x)); return r; }

__device__ __forceinline__ ull pk2(float lo, float hi) {
    ull r; asm("mov.b64 %0, {%1, %2};" : "=l"(r) : "f"(lo), "f"(hi)); return r;
}
__device__ __forceinline__ float2 upk2(ull v) {
    float2 f; asm("mov.b64 {%0, %1}, %2;" : "=f"(f.x), "=f"(f.y) : "l"(v)); return f;
}
__device__ __forceinline__ ull mul2_(ull a, ull b) {
    ull r; asm("mul.rn.f32x2 %0, %1, %2;" : "=l"(r) : "l"(a), "l"(b)); return r;
}
__device__ __forceinline__ ull add2_(ull a, ull b) {
    ull r; asm("add.rn.f32x2 %0, %1, %2;" : "=l"(r) : "l"(a), "l"(b)); return r;
}
__device__ __forceinline__ ull fma2_(ull a, ull b, ull c) {
    ull r; asm("fma.rn.f32x2 %0, %1, %2, %3;" : "=l"(r) : "l"(a), "l"(b), "l"(c)); return r;
}

// Uniform-grid fast path, constant-multiplier recurrence:
//   g_b = g0 * E^b * T_b,  E = exp(z0*delta) const/thread,  T_b = exp(-b^2 d^2/2)
//   data-independent -> folded into staged weights. Packed f32x2 lanes =
//   (fwd chain, bwd chain) of one trajectory; staged pair (w_k*T_k, w_{33-k}*T_k)
//   -> 1 LDS.64 per k serves both trajectories. Moments + U-trick:
//   F = (z0-17d)*S0f + (z0-16d)*S0b + d*(Uf - Ub);  coef = (K/sigma^2)*F/dist.
// KEY vs R16: weight LDGs hoisted into registers BEFORE the uniform-check
// barrier so DRAM latency overlaps the prologue instead of serializing.
__global__ __launch_bounds__(256, 5) void force_folder_kernel(
    const float* __restrict__ coords,   // [NT, NRES, 3]
    const float* __restrict__ gw,       // [NRES, NRES, NBINS]
    const float* __restrict__ centres,  // [NBINS]
    const float* __restrict__ sigmas,   // [NBINS]
    float* __restrict__ out)            // [NT, NRES, 3], pre-zeroed
{
    const int chunk = blockIdx.x;
    const int j     = blockIdx.y;
    const int tid   = threadIdx.x;
    const int warp  = tid >> 5;
    const int lane  = tid & 31;
    const int tg    = tid >> 6;     // 0..3 -> trajs {2tg, 2tg+1}
    const int il    = tid & 63;     // i-row lane

    __shared__ float2 s_wt[ROWS * WP2];  // (wT_fwd_k, wT_bwd_k) per row
    __shared__ float  s_T[NHALF];
    __shared__ float  s_cbj[NT * 3];
    __shared__ float  s_part[8][6];

    // ---- HOISTED gmem gather: issue all weight LDGs first (latency overlap)
    float2 wreg[5];
    {
        const int rbase = warp * 8;
        #pragma unroll
        for (int it = 0; it < 5; it++) {
            int k = it * 32 + lane;
            if (k < 8 * 17) {
                int r = k / 17;
                int c = k - r * 17;
                int rg2 = min(chunk * ROWS + rbase + r, NRES - 1);
                wreg[it] = *(const float2*)(gw + ((long)rg2 * NRES + j) * NBINS + 2 * c);
            }
        }
    }

    const float c0 = __ldg(centres);
    const float dc = __ldg(centres + 1) - c0;
    const float sg = __ldg(sigmas);
    const float invs  = 1.0f / sg;
    const float delta = dc * invs;
    const float Cq    = -0.72134752044f;              // -0.5 * log2(e)
    const float A     = delta * 1.44269504089f;       // delta * log2(e)

    if (tid < NT * 3) {
        int t = tid / 3, cc = tid - t * 3;
        s_cbj[tid] = coords[(t * NRES + j) * 3 + cc];
    }
    if (tid < NHALF) {
        float kd = (float)tid * delta;
        s_T[tid] = ex2a(Cq * kd * kd);               // T_k = exp(-k^2 d^2 / 2)
    }
    int okp = 1;
    if (tid < NBINS) {
        float cb = __ldg(centres + tid);
        float sb = __ldg(sigmas + tid);
        okp = (fabsf(sb - sg) <= 1e-5f * fabsf(sg)) &&
              (fabsf(cb - fmaf((float)tid, dc, c0)) <= 1e-4f * (fabsf(cb) + 1.0f));
    }
    const int uniform = __syncthreads_and(okp);      // orders s_T for the scatter

    // ---- Scatter staged weights (registers -> smem), T folded in ----
    {
        float* swf = (float*)s_wt;
        const int rbase = warp * 8;
        #pragma unroll
        for (int it = 0; it < 5; it++) {
            int k = it * 32 + lane;
            if (k < 8 * 17) {
                int r = k / 17;
                int c = k - r * 17;
                int rl = rbase + r;
                int b0 = 2 * c, b1 = 2 * c + 1;
                int e0 = min(b0, 33 - b0), h0 = (b0 > 16);
                int e1 = min(b1, 33 - b1), h1 = (b1 > 16);
                float t0 = uniform ? s_T[e0] : 1.0f;
                float t1 = uniform ? s_T[e1] : 1.0f;
                swf[(rl * WP2 + e0) * 2 + h0] = wreg[it].x * t0;
                swf[(rl * WP2 + e1) * 2 + h1] = wreg[it].y * t1;
            }
        }
    }
    __syncthreads();

    float acc[2][3];
    #pragma unroll
    for (int tl = 0; tl < 2; tl++) { acc[tl][0] = 0.f; acc[tl][1] = 0.f; acc[tl][2] = 0.f; }

    const int i = chunk * ROWS + il;
    if (i < NRES) {
        const float2* __restrict__ wrow2 = s_wt + il * WP2;

        float d[2], F[2], dxs[2], dys[2], dzs[2];
        #pragma unroll
        for (int tl = 0; tl < 2; tl++) {
            int t = tg * 2 + tl;
            const float* ci = coords + (t * NRES + i) * 3;
            float dx = s_cbj[t * 3 + 0] - ci[0];
            float dy = s_cbj[t * 3 + 1] - ci[1];
            float dz = s_cbj[t * 3 + 2] - ci[2];
            dxs[tl] = dx; dys[tl] = dy; dzs[tl] = dz;
            float ss = fmaf(dx, dx, fmaf(dy, dy, dz * dz));
            d[tl] = fminf(fmaxf(fsqrta(ss), 0.1f), 40.0f);
        }

        float cs;   // final: coef = cs * F * (1/dist)
        if (uniform) {
            const float mc0 = -c0 * invs;
            float z0s[2];
            ull P2[2], E2[2], S0[2], U2[2];
            #pragma unroll
            for (int tl = 0; tl < 2; tl++) {
                float z0  = fmaf(d[tl], invs, mc0);
                float z33 = z0 - 33.0f * delta;
                z0s[tl] = z0;
                P2[tl] = pk2(ex2a(Cq * z0 * z0), ex2a(Cq * z33 * z33));
                E2[tl] = pk2(ex2a(z0 * A),       ex2a(-z33 * A));
                S0[tl] = 0ull;
                U2[tl] = 0ull;
            }

            #pragma unroll
            for (int k = 0; k < NHALF; k++) {
                ull wt = *(const ull*)&wrow2[k];     // (wT_fwd_k, wT_bwd_k)
                #pragma unroll
                for (int tl = 0; tl < 2; tl++) {
                    S0[tl] = fma2_(wt, P2[tl], S0[tl]);
                    U2[tl] = add2_(U2[tl], S0[tl]);
                    P2[tl] = mul2_(P2[tl], E2[tl]);
                }
            }

            #pragma unroll
            for (int tl = 0; tl < 2; tl++) {
                float2 s0 = upk2(S0[tl]);            // (S0f, S0b)
                float2 uu = upk2(U2[tl]);            // (Uf, Ub)
                float e0 = z0s[tl] - 17.0f * delta;
                float e1 = z0s[tl] - 16.0f * delta;
                F[tl] = fmaf(e0, s0.x, fmaf(e1, s0.y, delta * (uu.x - uu.y)));
            }
            cs = KCB * invs * invs;
        } else {
            // generic fallback (non-uniform bins): reference-accurate scalar path
            F[0] = 0.0f; F[1] = 0.0f;
            for (int b = 0; b < NBINS; b++) {
                float cb  = __ldg(centres + b);
                float sb  = __ldg(sigmas + b);
                float isb = 1.0f / sb;
                float2 wp = wrow2[min(b, 33 - b)];
                float w   = ((b <= 16) ? wp.x : wp.y) * isb * isb * isb;
                #pragma unroll
                for (int tl = 0; tl < 2; tl++) {
                    float u = (d[tl] - cb) * isb;
                    float e = ex2a(Cq * u * u);
                    F[tl] = fmaf(-u * w, e, F[tl]);
                }
            }
            cs = -KCB;
        }

        #pragma unroll
        for (int tl = 0; tl < 2; tl++) {
            float coef = cs * F[tl] * frcpa(d[tl]);
            acc[tl][0] = fmaf(coef, dxs[tl], acc[tl][0]);
            acc[tl][1] = fmaf(coef, dys[tl], acc[tl][1]);
            acc[tl][2] = fmaf(coef, dzs[tl], acc[tl][2]);
        }
    }

    // ---- Reduce 32 i-lanes per warp; 2 warps per tg; atomic to out ----
    #pragma unroll
    for (int tl = 0; tl < 2; tl++) {
        #pragma unroll
        for (int c = 0; c < 3; c++) {
            float val = acc[tl][c];
            val += __shfl_down_sync(0xffffffffu, val, 16);
            val += __shfl_down_sync(0xffffffffu, val, 8);
            val += __shfl_down_sync(0xffffffffu, val, 4);
            val += __shfl_down_sync(0xffffffffu, val, 2);
            val += __shfl_down_sync(0xffffffffu, val, 1);
            if (lane == 0) s_part[warp][tl * 3 + c] = val;
        }
    }
    __syncthreads();
    if (tid < 24) {
        int tg2 = tid / 6, idx = tid - tg2 * 6;
        float s = s_part[tg2 * 2 + 0][idx] + s_part[tg2 * 2 + 1][idx];
        int tl = idx / 3, c = idx - tl * 3;
        int t = tg2 * 2 + tl;
        atomicAdd(&out[(t * NRES + j) * 3 + c], s);
    }
}

extern "C" void kernel_launch(void* const* d_in, const int* in_sizes, int n_in,
                              void* d_out, int out_size) {
    const float* coords  = (const float*)d_in[0];
    const float* gw      = (const float*)d_in[1];
    const float* centres = (const float*)d_in[2];
    const float* sigmas  = (const float*)d_in[3];
    float* out = (float*)d_out;

    cudaMemsetAsync(out, 0, (size_t)out_size * sizeof(float));  // graph memset node
    dim3 grid(NCHUNK, NRES);
    force_folder_kernel<<<grid, 256>>>(coords, gw, centres, sigmas, out);
}